// round 14
// baseline (speedup 1.0000x reference)
#include <cuda_runtime.h>
#include <cuda_bf16.h>
#include <cstdint>

// Problem constants
#define NUM_QT   65
#define NUM_OT   151
#define PAIR_NUM 90
#define BATCH    8192
#define BOX      10
#define TOTAL_ELEMS (NUM_QT * PAIR_NUM * NUM_OT * NUM_OT)  // 133,385,850
#define N4_TOTAL (TOTAL_ELEMS / 4)                         // 33,346,462 (tail = 2)

// Scratch: batch ids sorted (grouped) by qus_type. __device__ global = allowed.
__device__ int d_sorted_batch[BATCH];

// ---------------------------------------------------------------------------
// Kernel 1: grid-stride float4 copy score_matrix -> out (proven-best form).
// ---------------------------------------------------------------------------
__global__ void __launch_bounds__(256) copy_kernel(
    const float4* __restrict__ src4,
    float4* __restrict__ dst4,
    const float* __restrict__ src,
    float* __restrict__ dst)
{
    const int stride = gridDim.x * blockDim.x;
    for (int i = blockIdx.x * blockDim.x + threadIdx.x; i < N4_TOTAL; i += stride) {
        dst4[i] = src4[i];
    }
    // Scalar tail (TOTAL_ELEMS - 4*N4_TOTAL = 2 elements)
    if (blockIdx.x == 0 && threadIdx.x < (TOTAL_ELEMS - 4 * N4_TOTAL)) {
        int e = 4 * N4_TOTAL + threadIdx.x;
        dst[e] = src[e];
    }
}

// ---------------------------------------------------------------------------
// Kernel S: single-block counting sort of batch ids by qus_type (65 buckets).
// Runs on a side stream concurrent with the copy (reads only 32 KB).
// Within-bucket order is nondeterministic but irrelevant (scatter adds are
// order-independent up to fp rounding, same as plain atomics).
// ---------------------------------------------------------------------------
__global__ void __launch_bounds__(256) sort_kernel(const int* __restrict__ qus_type)
{
    __shared__ int h[NUM_QT];
    __shared__ int base[NUM_QT];
    int tid = threadIdx.x;

    for (int q = tid; q < NUM_QT; q += 256) h[q] = 0;
    __syncthreads();
    for (int b = tid; b < BATCH; b += 256)
        atomicAdd(&h[qus_type[b]], 1);
    __syncthreads();
    if (tid == 0) {
        int acc = 0;
        for (int q = 0; q < NUM_QT; q++) { base[q] = acc; acc += h[q]; }
    }
    __syncthreads();
    for (int q = tid; q < NUM_QT; q += 256) h[q] = base[q];   // h reused as cursor
    __syncthreads();
    for (int b = tid; b < BATCH; b += 256) {
        int pos = atomicAdd(&h[qus_type[b]], 1);
        d_sorted_batch[pos] = b;
    }
}

// ---------------------------------------------------------------------------
// Kernel 2: locality-ordered scatter.
// idx = p * BATCH + g  (g = qt-sorted batch rank, fast axis) =>
// each 256-thread block's updates land in <=2 contiguous 91KB (qt,p) planes
// of the output -> ~4x better DRAM page reuse than batch-major order.
// ---------------------------------------------------------------------------
__global__ void __launch_bounds__(256) scatter_sorted_kernel(
    const int* __restrict__ obj_label,
    const int* __restrict__ qus_type,
    const float* __restrict__ attention,
    float* __restrict__ out)
{
    int idx = blockIdx.x * blockDim.x + threadIdx.x;
    if (idx >= BATCH * PAIR_NUM) return;

    int p = idx / BATCH;           // slow axis: pair index
    int g = idx - p * BATCH;       // fast axis: sorted batch rank
    int b = d_sorted_batch[g];

    int i = p / (BOX - 1);
    int jr = p - i * (BOX - 1);
    int j = jr + (jr >= i ? 1 : 0);

    int qt  = __ldg(&qus_type[b]);
    int oli = __ldg(&obj_label[b * BOX + i]);
    int olj = __ldg(&obj_label[b * BOX + j]);
    float ai = __ldg(&attention[b * BOX + i]);
    float aj = __ldg(&attention[b * BOX + j]);

    // offset = ((qt*PAIR + p)*NUM_OT + label[j])*NUM_OT + label[i]  (fits int32)
    int off = ((qt * PAIR_NUM + p) * NUM_OT + olj) * NUM_OT + oli;
    atomicAdd(out + off, ai * aj);   // result unused -> REDG
}

// ---------------------------------------------------------------------------
// Launch:
//   stream 0:  copy (169us)
//   side:      sort_kernel (few us, hidden under copy)
//   join, then scatter_sorted on stream 0.
//
// Inputs (metadata order):
//   d_in[0] = obj_label    int32   [8192,10]
//   d_in[1] = qus_type     int32   [8192]
//   d_in[2] = attention    float32 [8192,10]
//   d_in[3] = score_matrix float32 [65,90,151,151]
// ---------------------------------------------------------------------------
extern "C" void kernel_launch(void* const* d_in, const int* in_sizes, int n_in,
                              void* d_out, int out_size)
{
    const int*   obj_label = (const int*)d_in[0];
    const int*   qus_type  = (const int*)d_in[1];
    const float* attention = (const float*)d_in[2];
    const float* score     = (const float*)d_in[3];
    float*       out       = (float*)d_out;

    // Lazy one-time resource setup (first call = uncaptured correctness run).
    static cudaStream_t s_side = nullptr;
    static cudaEvent_t  ev_fork = nullptr, ev_sort = nullptr;
    if (s_side == nullptr) {
        cudaStreamCreateWithFlags(&s_side, cudaStreamNonBlocking);
        cudaEventCreateWithFlags(&ev_fork, cudaEventDisableTiming);
        cudaEventCreateWithFlags(&ev_sort, cudaEventDisableTiming);
    }

    // Fork: sort batches by qt on the side stream (hidden under the copy).
    cudaEventRecord(ev_fork, 0);
    cudaStreamWaitEvent(s_side, ev_fork, 0);
    sort_kernel<<<1, 256, 0, s_side>>>(qus_type);
    cudaEventRecord(ev_sort, s_side);

    // Bulk copy on stream 0 (best measured: ~6.3 TB/s).
    copy_kernel<<<148 * 16, 256>>>((const float4*)score, (float4*)out, score, out);

    // Join, then locality-ordered scatter.
    cudaStreamWaitEvent(0, ev_sort, 0);
    {
        int total = BATCH * PAIR_NUM;  // 737,280
        int blocks = (total + 255) / 256;
        scatter_sorted_kernel<<<blocks, 256>>>(obj_label, qus_type, attention, out);
    }
}